// round 1
// baseline (speedup 1.0000x reference)
#include <cuda_runtime.h>

// Problem constants
#define Bb 4
#define Ss 2048
#define Dd 1024
#define Hh 16
#define DHd 64
#define Mm (Bb*Ss)   // 8192

// Scratch (allocation-free: __device__ globals)
__device__ float g_q[(size_t)Bb*Hh*Ss*DHd];
__device__ float g_k[(size_t)Bb*Hh*Ss*DHd];
__device__ float g_v[(size_t)Bb*Hh*Ss*DHd];
__device__ float g_ctx[(size_t)Mm*Dd];

// ---------------- SGEMM core: C[m,n] = sum_k A[m,k]*W[n,k] ----------------
#define BM 128
#define BN 128
#define BK 16

__device__ __forceinline__ void gemm_acc(
    const float* __restrict__ A, const float* __restrict__ W,
    float (*As)[BM], float (*Bs)[BN],
    int bm, int bn, float (&acc)[8][8])
{
    const int K = Dd;
    const int tid = threadIdx.x;
    const int lr0 = tid >> 2;          // 0..63
    const int lc4 = (tid & 3) * 4;     // 0,4,8,12
    const int tx = tid & 15;
    const int ty = tid >> 4;

    float4 pa[2], pb[2];
    #pragma unroll
    for (int i = 0; i < 2; i++) {
        int row = lr0 + i * 64;
        pa[i] = *(const float4*)&A[(size_t)(bm + row) * K + lc4];
        pb[i] = *(const float4*)&W[(size_t)(bn + row) * K + lc4];
    }

    for (int k0 = 0; k0 < K; k0 += BK) {
        // commit prefetched tile to smem
        #pragma unroll
        for (int i = 0; i < 2; i++) {
            int row = lr0 + i * 64;
            As[lc4 + 0][row] = pa[i].x; As[lc4 + 1][row] = pa[i].y;
            As[lc4 + 2][row] = pa[i].z; As[lc4 + 3][row] = pa[i].w;
            Bs[lc4 + 0][row] = pb[i].x; Bs[lc4 + 1][row] = pb[i].y;
            Bs[lc4 + 2][row] = pb[i].z; Bs[lc4 + 3][row] = pb[i].w;
        }
        __syncthreads();

        // prefetch next tile (overlaps with compute below)
        if (k0 + BK < K) {
            #pragma unroll
            for (int i = 0; i < 2; i++) {
                int row = lr0 + i * 64;
                pa[i] = *(const float4*)&A[(size_t)(bm + row) * K + (k0 + BK) + lc4];
                pb[i] = *(const float4*)&W[(size_t)(bn + row) * K + (k0 + BK) + lc4];
            }
        }

        #pragma unroll
        for (int kk = 0; kk < BK; kk++) {
            float a[8], b[8];
            *(float4*)&a[0] = *(const float4*)&As[kk][ty * 8];
            *(float4*)&a[4] = *(const float4*)&As[kk][ty * 8 + 4];
            *(float4*)&b[0] = *(const float4*)&Bs[kk][tx * 8];
            *(float4*)&b[4] = *(const float4*)&Bs[kk][tx * 8 + 4];
            #pragma unroll
            for (int i = 0; i < 8; i++)
                #pragma unroll
                for (int j = 0; j < 8; j++)
                    acc[i][j] += a[i] * b[j];
        }
        __syncthreads();
    }
}

// ---------------- QKV projection, epilogue -> [B,H,S,Dh] ----------------
__global__ void __launch_bounds__(256)
qkv_kernel(const float* __restrict__ x,
           const float* __restrict__ Wq, const float* __restrict__ bq,
           const float* __restrict__ Wk, const float* __restrict__ bk,
           const float* __restrict__ Wv, const float* __restrict__ bv)
{
    __shared__ float As[BK][BM];
    __shared__ float Bs[BK][BN];

    const float* W; const float* bias; float* out;
    if (blockIdx.z == 0)      { W = Wq; bias = bq; out = g_q; }
    else if (blockIdx.z == 1) { W = Wk; bias = bk; out = g_k; }
    else                      { W = Wv; bias = bv; out = g_v; }

    const int bm = blockIdx.y * BM;
    const int bn = blockIdx.x * BN;

    float acc[8][8] = {};
    gemm_acc(x, W, As, Bs, bm, bn, acc);

    const int tx = threadIdx.x & 15;
    const int ty = threadIdx.x >> 4;
    #pragma unroll
    for (int i = 0; i < 8; i++) {
        int m = bm + ty * 8 + i;
        int b = m >> 11;          // / 2048
        int s = m & 2047;
        #pragma unroll
        for (int j4 = 0; j4 < 2; j4++) {
            int n = bn + tx * 8 + j4 * 4;
            int h = n >> 6;
            int d = n & 63;
            float4 v;
            v.x = acc[i][j4 * 4 + 0] + bias[n + 0];
            v.y = acc[i][j4 * 4 + 1] + bias[n + 1];
            v.z = acc[i][j4 * 4 + 2] + bias[n + 2];
            v.w = acc[i][j4 * 4 + 3] + bias[n + 3];
            *(float4*)&out[((size_t)((b * Hh + h) * Ss + s)) * DHd + d] = v;
        }
    }
}

// ---------------- Output projection, plain epilogue -> d_out ----------------
__global__ void __launch_bounds__(256)
oproj_kernel(const float* __restrict__ Wo, const float* __restrict__ bo,
             float* __restrict__ out)
{
    __shared__ float As[BK][BM];
    __shared__ float Bs[BK][BN];

    const int bm = blockIdx.y * BM;
    const int bn = blockIdx.x * BN;

    float acc[8][8] = {};
    gemm_acc(g_ctx, Wo, As, Bs, bm, bn, acc);

    const int tx = threadIdx.x & 15;
    const int ty = threadIdx.x >> 4;
    #pragma unroll
    for (int i = 0; i < 8; i++) {
        int m = bm + ty * 8 + i;
        #pragma unroll
        for (int j4 = 0; j4 < 2; j4++) {
            int n = bn + tx * 8 + j4 * 4;
            float4 v;
            v.x = acc[i][j4 * 4 + 0] + bo[n + 0];
            v.y = acc[i][j4 * 4 + 1] + bo[n + 1];
            v.z = acc[i][j4 * 4 + 2] + bo[n + 2];
            v.w = acc[i][j4 * 4 + 3] + bo[n + 3];
            *(float4*)&out[(size_t)m * Dd + n] = v;
        }
    }
}

// ---------------- Flash attention: 1 thread = 1 query row ----------------
#define KT 16

__global__ void __launch_bounds__(128)
attn_kernel()
{
    __shared__ float4 Ks[KT * DHd / 4];   // 256 float4 = 4KB
    __shared__ float4 Vs[KT * DHd / 4];

    const int tid = threadIdx.x;
    const int bh = blockIdx.y;                       // b*16 + h
    const int qrow = blockIdx.x * 128 + tid;

    const float4* qp = (const float4*)(g_q + ((size_t)bh * Ss + qrow) * DHd);
    const float4* Kg = (const float4*)(g_k + (size_t)bh * Ss * DHd);
    const float4* Vg = (const float4*)(g_v + (size_t)bh * Ss * DHd);

    float q[64];
    #pragma unroll
    for (int d4 = 0; d4 < 16; d4++) *(float4*)&q[d4 * 4] = qp[d4];

    float acc[64];
    #pragma unroll
    for (int d = 0; d < 64; d++) acc[d] = 0.f;
    float mx = -1e30f, l = 0.f;

    for (int kt = 0; kt < Ss; kt += KT) {
        __syncthreads();
        #pragma unroll
        for (int i = 0; i < 2; i++) {
            int idx = tid + i * 128;
            Ks[idx] = Kg[kt * 16 + idx];
            Vs[idx] = Vg[kt * 16 + idx];
        }
        __syncthreads();

        float sc[KT];
        #pragma unroll
        for (int j = 0; j < KT; j++) {
            float s0 = 0.f, s1 = 0.f, s2 = 0.f, s3 = 0.f;
            #pragma unroll
            for (int d4 = 0; d4 < 16; d4++) {
                float4 kk = Ks[j * 16 + d4];
                s0 += q[d4 * 4 + 0] * kk.x;
                s1 += q[d4 * 4 + 1] * kk.y;
                s2 += q[d4 * 4 + 2] * kk.z;
                s3 += q[d4 * 4 + 3] * kk.w;
            }
            sc[j] = (s0 + s1 + s2 + s3) * 0.125f;   // 1/sqrt(64)
        }

        float mnew = mx;
        #pragma unroll
        for (int j = 0; j < KT; j++) mnew = fmaxf(mnew, sc[j]);
        float corr = __expf(mx - mnew);
        mx = mnew;
        float lsum = 0.f;
        #pragma unroll
        for (int j = 0; j < KT; j++) { sc[j] = __expf(sc[j] - mx); lsum += sc[j]; }
        l = l * corr + lsum;
        #pragma unroll
        for (int d = 0; d < 64; d++) acc[d] *= corr;

        #pragma unroll
        for (int j = 0; j < KT; j++) {
            float p = sc[j];
            #pragma unroll
            for (int d4 = 0; d4 < 16; d4++) {
                float4 vv = Vs[j * 16 + d4];
                acc[d4 * 4 + 0] += p * vv.x;
                acc[d4 * 4 + 1] += p * vv.y;
                acc[d4 * 4 + 2] += p * vv.z;
                acc[d4 * 4 + 3] += p * vv.w;
            }
        }
    }

    const float inv = 1.f / l;
    const int b = bh >> 4, h = bh & 15;
    float* outp = g_ctx + ((size_t)(b * Ss + qrow)) * Dd + h * DHd;
    #pragma unroll
    for (int d4 = 0; d4 < 16; d4++) {
        float4 v;
        v.x = acc[d4 * 4 + 0] * inv;
        v.y = acc[d4 * 4 + 1] * inv;
        v.z = acc[d4 * 4 + 2] * inv;
        v.w = acc[d4 * 4 + 3] * inv;
        ((float4*)outp)[d4] = v;
    }
}

// ---------------- launch ----------------
extern "C" void kernel_launch(void* const* d_in, const int* in_sizes, int n_in,
                              void* d_out, int out_size)
{
    const float* x  = (const float*)d_in[0];
    const float* Wq = (const float*)d_in[1];
    const float* bq = (const float*)d_in[2];
    const float* Wk = (const float*)d_in[3];
    const float* bk = (const float*)d_in[4];
    const float* Wv = (const float*)d_in[5];
    const float* bv = (const float*)d_in[6];
    const float* Wo = (const float*)d_in[7];
    const float* bo = (const float*)d_in[8];
    float* out = (float*)d_out;

    dim3 gQKV(Dd / BN, Mm / BM, 3);        // (8, 64, 3)
    qkv_kernel<<<gQKV, 256>>>(x, Wq, bq, Wk, bk, Wv, bv);

    dim3 gAtt(Ss / 128, Bb * Hh);          // (16, 64)
    attn_kernel<<<gAtt, 128>>>();

    dim3 gO(Dd / BN, Mm / BM);             // (8, 64)
    oproj_kernel<<<gO, 256>>>(Wo, bo, out);
}

// round 2
// speedup vs baseline: 3.9485x; 3.9485x over previous
#include <cuda_runtime.h>

#define Bb 4
#define Ss 2048
#define Dd 1024
#define Hh 16
#define DHd 64
#define Mm (Bb*Ss)   // 8192

// Scratch (allocation-free)
__device__ float g_q[(size_t)Bb*Hh*Ss*DHd];
__device__ float g_k[(size_t)Bb*Hh*Ss*DHd];
__device__ float g_v[(size_t)Bb*Hh*Ss*DHd];
__device__ float g_ctx[(size_t)Mm*Dd];

__device__ __forceinline__ unsigned f2tf(float f) {
    unsigned u; asm("cvt.rna.tf32.f32 %0, %1;" : "=r"(u) : "f"(f)); return u;
}
__device__ __forceinline__ float f2tff(float f) { return __uint_as_float(f2tf(f)); }
__device__ __forceinline__ unsigned su(float f) { return __float_as_uint(f); }

__device__ __forceinline__ void mma_tf32(float* c, unsigned a0, unsigned a1,
                                         unsigned a2, unsigned a3,
                                         unsigned b0, unsigned b1) {
    asm volatile(
        "mma.sync.aligned.m16n8k8.row.col.f32.tf32.tf32.f32 "
        "{%0,%1,%2,%3},{%4,%5,%6,%7},{%8,%9},{%0,%1,%2,%3};"
        : "+f"(c[0]), "+f"(c[1]), "+f"(c[2]), "+f"(c[3])
        : "r"(a0), "r"(a1), "r"(a2), "r"(a3), "r"(b0), "r"(b1));
}

// ============ TF32 GEMM core: C[m,n] = sum_k A[m,k]*W[n,k] ============
// Block 256 thr (8 warps, 2x4), tile 128x128, BK=32. Smem stride 36 (conflict-free frags).
#define GST 36

__device__ __forceinline__ void gemm_core(
    const float* __restrict__ A, const float* __restrict__ W,
    float* As, float* Bs, int bm, int bn, float acc[4][4][4])
{
    const int tid = threadIdx.x;
    const int lane = tid & 31, wid = tid >> 5;
    const int wm = wid >> 2, wn = wid & 3;
    const int lr = lane >> 2, lc = lane & 3;

    float4 pa[4], pb[4];
    #pragma unroll
    for (int i = 0; i < 4; i++) {
        int f = tid + i * 256, row = f >> 3, c4 = (f & 7) * 4;
        pa[i] = *(const float4*)&A[(bm + row) * Dd + c4];
        pb[i] = *(const float4*)&W[(bn + row) * Dd + c4];
    }

    for (int k0 = 0; k0 < Dd; k0 += 32) {
        #pragma unroll
        for (int i = 0; i < 4; i++) {
            int f = tid + i * 256, row = f >> 3, c4 = (f & 7) * 4;
            float4 va = pa[i], vb = pb[i];
            *(float4*)&As[row * GST + c4] =
                make_float4(f2tff(va.x), f2tff(va.y), f2tff(va.z), f2tff(va.w));
            *(float4*)&Bs[row * GST + c4] =
                make_float4(f2tff(vb.x), f2tff(vb.y), f2tff(vb.z), f2tff(vb.w));
        }
        __syncthreads();

        if (k0 + 32 < Dd) {
            #pragma unroll
            for (int i = 0; i < 4; i++) {
                int f = tid + i * 256, row = f >> 3, c4 = (f & 7) * 4;
                pa[i] = *(const float4*)&A[(bm + row) * Dd + k0 + 32 + c4];
                pb[i] = *(const float4*)&W[(bn + row) * Dd + k0 + 32 + c4];
            }
        }

        #pragma unroll
        for (int kk = 0; kk < 4; kk++) {
            unsigned af[4][4], bf[4][2];
            const float* Ab = As + (wm * 64 + lr) * GST + kk * 8 + lc;
            #pragma unroll
            for (int mt = 0; mt < 4; mt++) {
                af[mt][0] = su(Ab[mt * 16 * GST]);
                af[mt][1] = su(Ab[mt * 16 * GST + 8 * GST]);
                af[mt][2] = su(Ab[mt * 16 * GST + 4]);
                af[mt][3] = su(Ab[mt * 16 * GST + 8 * GST + 4]);
            }
            const float* Bp = Bs + (wn * 32 + lr) * GST + kk * 8 + lc;
            #pragma unroll
            for (int nt = 0; nt < 4; nt++) {
                bf[nt][0] = su(Bp[nt * 8 * GST]);
                bf[nt][1] = su(Bp[nt * 8 * GST + 4]);
            }
            #pragma unroll
            for (int mt = 0; mt < 4; mt++)
                #pragma unroll
                for (int nt = 0; nt < 4; nt++)
                    mma_tf32(acc[mt][nt], af[mt][0], af[mt][1], af[mt][2], af[mt][3],
                             bf[nt][0], bf[nt][1]);
        }
        __syncthreads();
    }
}

// ============ QKV projection ============
__global__ void __launch_bounds__(256)
qkv_kernel(const float* __restrict__ x,
           const float* __restrict__ Wq, const float* __restrict__ bq,
           const float* __restrict__ Wk, const float* __restrict__ bk,
           const float* __restrict__ Wv, const float* __restrict__ bv)
{
    __shared__ float As[128 * GST];
    __shared__ float Bs[128 * GST];

    const float* W; const float* bias; float* out;
    if (blockIdx.z == 0)      { W = Wq; bias = bq; out = g_q; }
    else if (blockIdx.z == 1) { W = Wk; bias = bk; out = g_k; }
    else                      { W = Wv; bias = bv; out = g_v; }

    const int bm = blockIdx.y * 128, bn = blockIdx.x * 128;
    float acc[4][4][4] = {};
    gemm_core(x, W, As, Bs, bm, bn, acc);

    const int lane = threadIdx.x & 31, wid = threadIdx.x >> 5;
    const int wm = wid >> 2, wn = wid & 3;
    const int lr = lane >> 2, lc = lane & 3;

    #pragma unroll
    for (int mt = 0; mt < 4; mt++) {
        #pragma unroll
        for (int half = 0; half < 2; half++) {
            int m = bm + wm * 64 + mt * 16 + lr + half * 8;
            int b = m >> 11, s = m & 2047;
            #pragma unroll
            for (int nt = 0; nt < 4; nt++) {
                int n = bn + wn * 32 + nt * 8 + 2 * lc;
                int h = n >> 6, d = n & 63;
                float2 v;
                v.x = f2tff(acc[mt][nt][half * 2 + 0] + bias[n]);
                v.y = f2tff(acc[mt][nt][half * 2 + 1] + bias[n + 1]);
                *(float2*)&out[(((b * Hh + h) * Ss + s)) * DHd + d] = v;
            }
        }
    }
}

// ============ Output projection ============
__global__ void __launch_bounds__(256)
oproj_kernel(const float* __restrict__ Wo, const float* __restrict__ bo,
             float* __restrict__ out)
{
    __shared__ float As[128 * GST];
    __shared__ float Bs[128 * GST];

    const int bm = blockIdx.y * 128, bn = blockIdx.x * 128;
    float acc[4][4][4] = {};
    gemm_core(g_ctx, Wo, As, Bs, bm, bn, acc);

    const int lane = threadIdx.x & 31, wid = threadIdx.x >> 5;
    const int wm = wid >> 2, wn = wid & 3;
    const int lr = lane >> 2, lc = lane & 3;

    #pragma unroll
    for (int mt = 0; mt < 4; mt++) {
        #pragma unroll
        for (int half = 0; half < 2; half++) {
            int m = bm + wm * 64 + mt * 16 + lr + half * 8;
            #pragma unroll
            for (int nt = 0; nt < 4; nt++) {
                int n = bn + wn * 32 + nt * 8 + 2 * lc;
                float2 v;
                v.x = acc[mt][nt][half * 2 + 0] + bo[n];
                v.y = acc[mt][nt][half * 2 + 1] + bo[n + 1];
                *(float2*)&out[m * Dd + n] = v;
            }
        }
    }
}

// ============ Flash attention (TF32 MMA) ============
// Block: 128 thr (4 warps), 64 q-rows per block, K-tile = 32 tokens.
// Warp w owns q rows [w*16, w*16+16).
#define KST 68
#define VST 72
#define PST 68

__global__ void __launch_bounds__(128)
attn_kernel()
{
    __shared__ float Ks[32 * KST];
    __shared__ float Vs[32 * VST];
    __shared__ float Ps[64 * PST];   // Q staging, then P tiles

    const int tid = threadIdx.x;
    const int lane = tid & 31, w = tid >> 5;
    const int lr = lane >> 2, lc = lane & 3;
    const int bh = blockIdx.y;
    const int qb = blockIdx.x * 64;

    const float* Qg = g_q + ((size_t)bh * Ss + qb) * DHd;
    const float* Kg = g_k + (size_t)bh * Ss * DHd;
    const float* Vg = g_v + (size_t)bh * Ss * DHd;

    // Stage Q -> smem -> frags (A-operand layout), 8 k-substeps of Dh=64
    #pragma unroll
    for (int i = 0; i < 8; i++) {
        int f = tid + i * 128, row = f >> 4, c4 = (f & 15) * 4;
        *(float4*)&Ps[row * PST + c4] = *(const float4*)&Qg[row * DHd + c4];
    }
    __syncthreads();
    unsigned qf[8][4];
    #pragma unroll
    for (int ks = 0; ks < 8; ks++) {
        const float* qp = Ps + (w * 16 + lr) * PST + ks * 8 + lc;
        qf[ks][0] = su(qp[0]);
        qf[ks][1] = su(qp[8 * PST]);
        qf[ks][2] = su(qp[4]);
        qf[ks][3] = su(qp[8 * PST + 4]);
    }
    __syncthreads();

    float acc_o[8][4] = {};
    float m0 = -1e30f, m1 = -1e30f, l0 = 0.f, l1 = 0.f;

    float4 pk[4], pv[4];
    #pragma unroll
    for (int i = 0; i < 4; i++) {
        int f = tid + i * 128, row = f >> 4, c4 = (f & 15) * 4;
        pk[i] = *(const float4*)&Kg[row * DHd + c4];
        pv[i] = *(const float4*)&Vg[row * DHd + c4];
    }

    for (int kt = 0; kt < Ss; kt += 32) {
        __syncthreads();   // prior iteration's smem reads complete
        #pragma unroll
        for (int i = 0; i < 4; i++) {
            int f = tid + i * 128, row = f >> 4, c4 = (f & 15) * 4;
            *(float4*)&Ks[row * KST + c4] = pk[i];
            *(float4*)&Vs[row * VST + c4] = pv[i];
        }
        __syncthreads();

        if (kt + 32 < Ss) {
            #pragma unroll
            for (int i = 0; i < 4; i++) {
                int f = tid + i * 128, row = f >> 4, c4 = (f & 15) * 4;
                pk[i] = *(const float4*)&Kg[(kt + 32 + row) * DHd + c4];
                pv[i] = *(const float4*)&Vg[(kt + 32 + row) * DHd + c4];
            }
        }

        // S = Q K^T  (64q x 32k per block, 16q x 32k per warp)
        float s[4][4] = {};
        #pragma unroll
        for (int ks = 0; ks < 8; ks++) {
            #pragma unroll
            for (int nt = 0; nt < 4; nt++) {
                const float* kp = Ks + (nt * 8 + lr) * KST + ks * 8 + lc;
                mma_tf32(s[nt], qf[ks][0], qf[ks][1], qf[ks][2], qf[ks][3],
                         su(kp[0]), su(kp[4]));
            }
        }
        #pragma unroll
        for (int nt = 0; nt < 4; nt++)
            #pragma unroll
            for (int j = 0; j < 4; j++)
                s[nt][j] *= 0.125f;   // 1/sqrt(64)

        // row-wise online softmax (rows lr and lr+8 of this warp's 16)
        float mx0 = -1e30f, mx1 = -1e30f;
        #pragma unroll
        for (int nt = 0; nt < 4; nt++) {
            mx0 = fmaxf(mx0, fmaxf(s[nt][0], s[nt][1]));
            mx1 = fmaxf(mx1, fmaxf(s[nt][2], s[nt][3]));
        }
        mx0 = fmaxf(mx0, __shfl_xor_sync(0xffffffff, mx0, 1));
        mx0 = fmaxf(mx0, __shfl_xor_sync(0xffffffff, mx0, 2));
        mx1 = fmaxf(mx1, __shfl_xor_sync(0xffffffff, mx1, 1));
        mx1 = fmaxf(mx1, __shfl_xor_sync(0xffffffff, mx1, 2));

        float mn0 = fmaxf(m0, mx0), mn1 = fmaxf(m1, mx1);
        float cr0 = __expf(m0 - mn0), cr1 = __expf(m1 - mn1);
        m0 = mn0; m1 = mn1;

        float ls0 = 0.f, ls1 = 0.f;
        float* pp0 = Ps + (w * 16 + lr) * PST + 2 * lc;
        float* pp1 = pp0 + 8 * PST;
        #pragma unroll
        for (int nt = 0; nt < 4; nt++) {
            float p00 = __expf(s[nt][0] - m0), p01 = __expf(s[nt][1] - m0);
            float p10 = __expf(s[nt][2] - m1), p11 = __expf(s[nt][3] - m1);
            ls0 += p00 + p01; ls1 += p10 + p11;
            *(float2*)&pp0[nt * 8] = make_float2(f2tff(p00), f2tff(p01));
            *(float2*)&pp1[nt * 8] = make_float2(f2tff(p10), f2tff(p11));
        }
        ls0 += __shfl_xor_sync(0xffffffff, ls0, 1);
        ls0 += __shfl_xor_sync(0xffffffff, ls0, 2);
        ls1 += __shfl_xor_sync(0xffffffff, ls1, 1);
        ls1 += __shfl_xor_sync(0xffffffff, ls1, 2);
        l0 = l0 * cr0 + ls0;
        l1 = l1 * cr1 + ls1;

        #pragma unroll
        for (int dt = 0; dt < 8; dt++) {
            acc_o[dt][0] *= cr0; acc_o[dt][1] *= cr0;
            acc_o[dt][2] *= cr1; acc_o[dt][3] *= cr1;
        }
        __syncwarp();

        // O += P V   (k-dim = 32 tokens, 4 substeps)
        #pragma unroll
        for (int ks = 0; ks < 4; ks++) {
            const float* pf = Ps + (w * 16 + lr) * PST + ks * 8 + lc;
            unsigned a0 = su(pf[0]), a1 = su(pf[8 * PST]);
            unsigned a2 = su(pf[4]), a3 = su(pf[8 * PST + 4]);
            #pragma unroll
            for (int dt = 0; dt < 8; dt++) {
                const float* vp = Vs + (ks * 8 + lc) * VST + dt * 8 + lr;
                mma_tf32(acc_o[dt], a0, a1, a2, a3, su(vp[0]), su(vp[4 * VST]));
            }
        }
    }

    const float inv0 = 1.f / l0, inv1 = 1.f / l1;
    const int b = bh >> 4, h = bh & 15;
    const int r0 = b * Ss + qb + w * 16 + lr;
    #pragma unroll
    for (int dt = 0; dt < 8; dt++) {
        int col = h * DHd + dt * 8 + 2 * lc;
        *(float2*)&g_ctx[(size_t)r0 * Dd + col] =
            make_float2(acc_o[dt][0] * inv0, acc_o[dt][1] * inv0);
        *(float2*)&g_ctx[(size_t)(r0 + 8) * Dd + col] =
            make_float2(acc_o[dt][2] * inv1, acc_o[dt][3] * inv1);
    }
}

// ============ launch ============
extern "C" void kernel_launch(void* const* d_in, const int* in_sizes, int n_in,
                              void* d_out, int out_size)
{
    const float* x  = (const float*)d_in[0];
    const float* Wq = (const float*)d_in[1];
    const float* bq = (const float*)d_in[2];
    const float* Wk = (const float*)d_in[3];
    const float* bk = (const float*)d_in[4];
    const float* Wv = (const float*)d_in[5];
    const float* bv = (const float*)d_in[6];
    const float* Wo = (const float*)d_in[7];
    const float* bo = (const float*)d_in[8];
    float* out = (float*)d_out;

    dim3 gQKV(Dd / 128, Mm / 128, 3);
    qkv_kernel<<<gQKV, 256>>>(x, Wq, bq, Wk, bk, Wv, bv);

    dim3 gAtt(Ss / 64, Bb * Hh);
    attn_kernel<<<gAtt, 128>>>();

    dim3 gO(Dd / 128, Mm / 128);
    oproj_kernel<<<gO, 256>>>(Wo, bo, out);
}